// round 3
// baseline (speedup 1.0000x reference)
#include <cuda_runtime.h>
#include <math.h>

// Problem dims (fixed by the dataset)
#define L_SEQ   4096
#define B_SZ    8
#define D_SZ    1024
#define N_HEADS 16

// Chunked-scan config: 32 chunks -> 2048 CTAs (fills the 8-CTA/SM reg ceiling)
#define NCHUNK  32
#define CHUNK   (L_SEQ / NCHUNK)   // 128
#define BD      (B_SZ * D_SZ)      // 8192
#define BDN     (B_SZ * D_SZ * N_HEADS)

typedef unsigned long long ull;

// Scratch (no cudaMalloc allowed) — coefficients + per-chunk states (16 MB)
__device__ float g_q[D_SZ * N_HEADS];
__device__ float g_c[D_SZ * N_HEADS];
__device__ float g_state[NCHUNK * BDN];

// ---------------------------------------------------------------------------
// Packed f32x2 helpers (Blackwell FFMA2 — ptxas will not auto-fuse; PTX only)
// ---------------------------------------------------------------------------
__device__ __forceinline__ ull fma2(ull a, ull b, ull c) {
    ull d;
    asm("fma.rn.f32x2 %0, %1, %2, %3;" : "=l"(d) : "l"(a), "l"(b), "l"(c));
    return d;
}
__device__ __forceinline__ ull pack2(float lo, float hi) {
    ull d;
    asm("mov.b64 %0, {%1, %2};" : "=l"(d) : "f"(lo), "f"(hi));
    return d;
}
__device__ __forceinline__ void unpack2(ull v, float& lo, float& hi) {
    asm("mov.b64 {%0, %1}, %2;" : "=f"(lo), "=f"(hi) : "l"(v));
}

// ---------------------------------------------------------------------------
// Phase 0: coefficients
//   p = sigmoid(damping); q = 1 - p*sigmoid(decay)  (q in (0,1))
//   c = p * ema * proj * (1/sqrt(N)) = p * ema * proj * 0.25
// ---------------------------------------------------------------------------
__global__ void coef_kernel(const float* __restrict__ damping,
                            const float* __restrict__ decay,
                            const float* __restrict__ ema,
                            const float* __restrict__ proj) {
    int i = blockIdx.x * blockDim.x + threadIdx.x;
    if (i >= D_SZ * N_HEADS) return;
    float p = 1.0f / (1.0f + expf(-damping[i]));
    float s = 1.0f / (1.0f + expf(-decay[i]));
    g_q[i] = 1.0f - p * s;
    g_c[i] = p * ema[i] * proj[i] * 0.25f;
}

// ---------------------------------------------------------------------------
// Phase 1: chunk-local scans with zero initial state; store final 16 states
//   h[n] <- q[n]*h[n] + x[l]   (8 packed f32x2 chains)
// grid: (D/128, B, NCHUNK), block: 128 (one thread per d)
// ---------------------------------------------------------------------------
__global__ void __launch_bounds__(128, 8) scan_local_kernel(const float* __restrict__ x) {
    const int d  = blockIdx.x * 128 + threadIdx.x;
    const int b  = blockIdx.y;
    const int ck = blockIdx.z;

    ull q2[8], h2[8];
    const ulonglong2* qv = (const ulonglong2*)(g_q + d * N_HEADS);
#pragma unroll
    for (int j = 0; j < 4; j++) {
        ulonglong2 v = qv[j];
        q2[2*j] = v.x; q2[2*j+1] = v.y;
    }
#pragma unroll
    for (int j = 0; j < 8; j++) h2[j] = 0ULL;

    const float* xp = x + (size_t)ck * CHUNK * BD + (size_t)b * D_SZ + d;
#pragma unroll 4
    for (int l = 0; l < CHUNK; l++) {
        float xv = __ldcs(xp + (size_t)l * BD);
        ull xx = pack2(xv, xv);
#pragma unroll
        for (int j = 0; j < 8; j++) h2[j] = fma2(q2[j], h2[j], xx);
    }

    ulonglong2* sp = (ulonglong2*)(g_state + ((size_t)(ck * B_SZ + b) * D_SZ + d) * N_HEADS);
#pragma unroll
    for (int j = 0; j < 4; j++) {
        ulonglong2 v; v.x = h2[2*j]; v.y = h2[2*j+1];
        sp[j] = v;
    }
}

// ---------------------------------------------------------------------------
// Phase 2: cross-chunk prefix (diagonal, decay factor q^CHUNK).
// In place: g_state[c] becomes the INITIAL state of chunk c.
//   H[0] = 0;  H[c] = q^CHUNK * H[c-1] + S_local[c-1]
// ---------------------------------------------------------------------------
__global__ void prefix_kernel() {
    int i = blockIdx.x * blockDim.x + threadIdx.x;
    if (i >= BDN) return;
    float q = g_q[i % (D_SZ * N_HEADS)];
    // q^128 by 7 squarings (q in (0,1))
    float qc = q;
#pragma unroll
    for (int k = 0; k < 7; k++) qc *= qc;

    float H = 0.0f;
#pragma unroll
    for (int c = 0; c < NCHUNK; c++) {
        float* ptr = g_state + (size_t)c * BDN + i;
        float S = *ptr;      // local final state of chunk c (zero-init)
        *ptr = H;            // initial state for chunk c
        H = fmaf(qc, H, S);  // carry to next chunk
    }
}

// ---------------------------------------------------------------------------
// Phase 3: full scan with correct initial state, fused projection+residual+relu
//   out[l,b,d] = relu( sum_n c[n]*h[n,l]  +  x[l,b,d]*rw[d] )
// ---------------------------------------------------------------------------
__global__ void __launch_bounds__(128, 8) scan_out_kernel(const float* __restrict__ x,
                                                          const float* __restrict__ rw,
                                                          float* __restrict__ out) {
    const int d  = blockIdx.x * 128 + threadIdx.x;
    const int b  = blockIdx.y;
    const int ck = blockIdx.z;

    ull q2[8], c2[8], h2[8];
    const ulonglong2* qv = (const ulonglong2*)(g_q + d * N_HEADS);
    const ulonglong2* cv = (const ulonglong2*)(g_c + d * N_HEADS);
    const ulonglong2* sv = (const ulonglong2*)(g_state + ((size_t)(ck * B_SZ + b) * D_SZ + d) * N_HEADS);
#pragma unroll
    for (int j = 0; j < 4; j++) {
        ulonglong2 vq = qv[j], vc = cv[j], vh = sv[j];
        q2[2*j] = vq.x; q2[2*j+1] = vq.y;
        c2[2*j] = vc.x; c2[2*j+1] = vc.y;
        h2[2*j] = vh.x; h2[2*j+1] = vh.y;
    }
    const float rw_d = rw[d];

    const size_t base = (size_t)ck * CHUNK * BD + (size_t)b * D_SZ + d;
    const float* xp = x + base;
    float*       op = out + base;

#pragma unroll 4
    for (int l = 0; l < CHUNK; l++) {
        float xv = __ldcs(xp + (size_t)l * BD);
        ull xx = pack2(xv, xv);
#pragma unroll
        for (int j = 0; j < 8; j++) h2[j] = fma2(q2[j], h2[j], xx);

        // projection: two packed accumulator chains for ILP
        ull s0 = 0ULL, s1 = 0ULL;
#pragma unroll
        for (int j = 0; j < 8; j += 2) {
            s0 = fma2(c2[j + 0], h2[j + 0], s0);
            s1 = fma2(c2[j + 1], h2[j + 1], s1);
        }
        float a0, a1, b0, b1;
        unpack2(s0, a0, a1);
        unpack2(s1, b0, b1);
        float val = fmaf(xv, rw_d, (a0 + a1) + (b0 + b1));
        __stcs(op + (size_t)l * BD, fmaxf(val, 0.0f));
    }
}

// ---------------------------------------------------------------------------
// Launch
// inputs: 0=x (L,B,D), 1=damping (D,N,1), 2=decay (D,N,1),
//         3=ema (D,N,1), 4=proj (D,N), 5=residual_weight (D,)
// ---------------------------------------------------------------------------
extern "C" void kernel_launch(void* const* d_in, const int* in_sizes, int n_in,
                              void* d_out, int out_size) {
    const float* x       = (const float*)d_in[0];
    const float* damping = (const float*)d_in[1];
    const float* decay   = (const float*)d_in[2];
    const float* ema     = (const float*)d_in[3];
    const float* proj    = (const float*)d_in[4];
    const float* rw      = (const float*)d_in[5];
    float* out = (float*)d_out;

    coef_kernel<<<(D_SZ * N_HEADS + 255) / 256, 256>>>(damping, decay, ema, proj);

    dim3 sgrid(D_SZ / 128, B_SZ, NCHUNK);
    scan_local_kernel<<<sgrid, 128>>>(x);

    prefix_kernel<<<(BDN + 255) / 256, 256>>>();

    scan_out_kernel<<<sgrid, 128>>>(x, rw, out);
}

// round 4
// speedup vs baseline: 1.5032x; 1.5032x over previous
#include <cuda_runtime.h>
#include <math.h>

// Problem dims (fixed by the dataset)
#define L_SEQ   4096
#define B_SZ    8
#define D_SZ    1024
#define N_HEADS 16

// Chunked-scan config: 32 chunks -> 2048 CTAs -> occupancy hits the
// 8-CTA/SM register ceiling (50%) instead of being grid-limited (41%).
#define NCHUNK  32
#define CHUNK   (L_SEQ / NCHUNK)   // 128
#define BD      (B_SZ * D_SZ)      // 8192
#define BDN     (B_SZ * D_SZ * N_HEADS)

// Scratch (no cudaMalloc allowed) — coefficients + per-chunk states
__device__ float g_q[D_SZ * N_HEADS];
__device__ float g_c[D_SZ * N_HEADS];
__device__ float g_state[NCHUNK * BDN];

// ---------------------------------------------------------------------------
// Phase 0: coefficients
//   p = sigmoid(damping); q = 1 - p*sigmoid(decay)  (q in (0,1))
//   c = p * ema * proj * (1/sqrt(N)) = p * ema * proj * 0.25
// ---------------------------------------------------------------------------
__global__ void coef_kernel(const float* __restrict__ damping,
                            const float* __restrict__ decay,
                            const float* __restrict__ ema,
                            const float* __restrict__ proj) {
    int i = blockIdx.x * blockDim.x + threadIdx.x;
    if (i >= D_SZ * N_HEADS) return;
    float p = 1.0f / (1.0f + expf(-damping[i]));
    float s = 1.0f / (1.0f + expf(-decay[i]));
    g_q[i] = 1.0f - p * s;
    g_c[i] = p * ema[i] * proj[i] * 0.25f;
}

// ---------------------------------------------------------------------------
// Phase 1: chunk-local scans with zero initial state; store final 16 states
//   h[n] <- q[n]*h[n] + x[l]
// grid: (D/128, B, NCHUNK), block: 128 (one thread per d)
// Memory-lean (16 FMA/elem): batch 8 loads up front for MLP=8.
// ---------------------------------------------------------------------------
__global__ void __launch_bounds__(128, 8) scan_local_kernel(const float* __restrict__ x) {
    const int d  = blockIdx.x * 128 + threadIdx.x;
    const int b  = blockIdx.y;
    const int ck = blockIdx.z;

    float q[N_HEADS], h[N_HEADS];
    const float4* qv = (const float4*)(g_q + d * N_HEADS);
#pragma unroll
    for (int j = 0; j < 4; j++) {
        float4 v = qv[j];
        q[4*j+0] = v.x; q[4*j+1] = v.y; q[4*j+2] = v.z; q[4*j+3] = v.w;
    }
#pragma unroll
    for (int n = 0; n < N_HEADS; n++) h[n] = 0.0f;

    const float* xp = x + (size_t)ck * CHUNK * BD + (size_t)b * D_SZ + d;

    for (int l0 = 0; l0 < CHUNK; l0 += 8) {
        float xv[8];
#pragma unroll
        for (int u = 0; u < 8; u++) xv[u] = xp[(size_t)(l0 + u) * BD];
#pragma unroll
        for (int u = 0; u < 8; u++) {
#pragma unroll
            for (int n = 0; n < N_HEADS; n++) h[n] = fmaf(q[n], h[n], xv[u]);
        }
    }

    float4* sp = (float4*)(g_state + ((size_t)(ck * B_SZ + b) * D_SZ + d) * N_HEADS);
#pragma unroll
    for (int j = 0; j < 4; j++)
        sp[j] = make_float4(h[4*j+0], h[4*j+1], h[4*j+2], h[4*j+3]);
}

// ---------------------------------------------------------------------------
// Phase 2: cross-chunk prefix (diagonal, decay factor q^CHUNK).
// In place: g_state[c] becomes the INITIAL state of chunk c.
//   H[0] = 0;  H[c] = q^CHUNK * H[c-1] + S_local[c-1]
// ---------------------------------------------------------------------------
__global__ void prefix_kernel() {
    int i = blockIdx.x * blockDim.x + threadIdx.x;
    if (i >= BDN) return;
    float q = g_q[i % (D_SZ * N_HEADS)];
    // q^128 by 7 squarings (CHUNK = 128, q in (0,1))
    float qc = q;
#pragma unroll
    for (int k = 0; k < 7; k++) qc *= qc;

    float H = 0.0f;
#pragma unroll
    for (int c = 0; c < NCHUNK; c++) {
        float* ptr = g_state + (size_t)c * BDN + i;
        float S = *ptr;      // local final state of chunk c (zero-init)
        *ptr = H;            // initial state for chunk c
        H = fmaf(qc, H, S);  // carry to next chunk
    }
}

// ---------------------------------------------------------------------------
// Phase 3: full scan with correct initial state, fused projection+residual+relu
//   out[l,b,d] = relu( sum_n c[n]*h[n,l]  +  x[l,b,d]*rw[d] )
// FMA-pipe bound (33 FMA/elem): unroll 4 with batched loads; fits 64 regs.
// ---------------------------------------------------------------------------
__global__ void __launch_bounds__(128, 8) scan_out_kernel(const float* __restrict__ x,
                                                          const float* __restrict__ rw,
                                                          float* __restrict__ out) {
    const int d  = blockIdx.x * 128 + threadIdx.x;
    const int b  = blockIdx.y;
    const int ck = blockIdx.z;

    float q[N_HEADS], c[N_HEADS], h[N_HEADS];
    const float4* qv = (const float4*)(g_q + d * N_HEADS);
    const float4* cv = (const float4*)(g_c + d * N_HEADS);
    const float4* sv = (const float4*)(g_state + ((size_t)(ck * B_SZ + b) * D_SZ + d) * N_HEADS);
#pragma unroll
    for (int j = 0; j < 4; j++) {
        float4 vq = qv[j], vc = cv[j], vh = sv[j];
        q[4*j+0] = vq.x; q[4*j+1] = vq.y; q[4*j+2] = vq.z; q[4*j+3] = vq.w;
        c[4*j+0] = vc.x; c[4*j+1] = vc.y; c[4*j+2] = vc.z; c[4*j+3] = vc.w;
        h[4*j+0] = vh.x; h[4*j+1] = vh.y; h[4*j+2] = vh.z; h[4*j+3] = vh.w;
    }
    const float rw_d = rw[d];

    const size_t base = (size_t)ck * CHUNK * BD + (size_t)b * D_SZ + d;
    const float* xp = x + base;
    float*       op = out + base;

    for (int l0 = 0; l0 < CHUNK; l0 += 4) {
        float xv[4];
#pragma unroll
        for (int u = 0; u < 4; u++) xv[u] = xp[(size_t)(l0 + u) * BD];
#pragma unroll
        for (int u = 0; u < 4; u++) {
#pragma unroll
            for (int n = 0; n < N_HEADS; n++) h[n] = fmaf(q[n], h[n], xv[u]);
            // projection: two accumulator chains for ILP
            float s0 = 0.0f, s1 = 0.0f;
#pragma unroll
            for (int n = 0; n < N_HEADS; n += 2) {
                s0 = fmaf(c[n + 0], h[n + 0], s0);
                s1 = fmaf(c[n + 1], h[n + 1], s1);
            }
            float val = fmaf(xv[u], rw_d, s0 + s1);
            op[(size_t)(l0 + u) * BD] = fmaxf(val, 0.0f);
        }
    }
}

// ---------------------------------------------------------------------------
// Launch
// inputs: 0=x (L,B,D), 1=damping (D,N,1), 2=decay (D,N,1),
//         3=ema (D,N,1), 4=proj (D,N), 5=residual_weight (D,)
// ---------------------------------------------------------------------------
extern "C" void kernel_launch(void* const* d_in, const int* in_sizes, int n_in,
                              void* d_out, int out_size) {
    const float* x       = (const float*)d_in[0];
    const float* damping = (const float*)d_in[1];
    const float* decay   = (const float*)d_in[2];
    const float* ema     = (const float*)d_in[3];
    const float* proj    = (const float*)d_in[4];
    const float* rw      = (const float*)d_in[5];
    float* out = (float*)d_out;

    coef_kernel<<<(D_SZ * N_HEADS + 255) / 256, 256>>>(damping, decay, ema, proj);

    dim3 sgrid(D_SZ / 128, B_SZ, NCHUNK);
    scan_local_kernel<<<sgrid, 128>>>(x);

    prefix_kernel<<<(BDN + 255) / 256, 256>>>();

    scan_out_kernel<<<sgrid, 128>>>(x, rw, out);
}